// round 4
// baseline (speedup 1.0000x reference)
#include <cuda_runtime.h>

#define NB    512   // batches
#define NL    512   // stream length (511 increments)
#define NC    8     // channels
#define NG    8     // chunk groups per block (Chen-associative split)
#define CHUNK 64    // increments per group (last group gets 63)
#define SIGSZ 584   // 8 + 64 + 512
#define S2OFF 8
#define S3OFF 72

// packed 2xfp32 fma: d = a*b + d (elementwise on both halves)
__device__ __forceinline__ void ffma2(unsigned long long& d,
                                      unsigned long long a,
                                      unsigned long long b) {
    asm("fma.rn.f32x2 %0, %1, %2, %0;" : "+l"(d) : "l"(a), "l"(b));
}

// ---------------------------------------------------------------------------
// One block = one batch. 512 threads = 8 groups x 64 threads.
// Group g computes the depth-3 signature of increments [g*64, g*64+len) with
// thread lt = i*8+c owning S2[i,c] and S3[i,c,0..7]. Then a 3-level Chen tree
// combine in shared memory folds the 8 segment signatures into one.
// ---------------------------------------------------------------------------
__global__ __launch_bounds__(512) void sig_fused_kernel(
    const float* __restrict__ path, float* __restrict__ out)
{
    const int b  = blockIdx.x;
    const int t  = threadIdx.x;      // 0..511
    const int g  = t >> 6;           // group 0..7
    const int lt = t & 63;           // 0..63
    const int i  = lt >> 3;
    const int c  = lt & 7;

    __shared__ __align__(16) float sinc[(NL - 1) * NC];   // 16352 B
    __shared__ __align__(16) float sseg[NG][SIGSZ];       // 18688 B

    const float* prow = path + (size_t)b * NL * NC;

    // Stage increments into shared (coalesced float4 global loads).
    if (t < NL - 1) {
        const float4* p = (const float4*)(prow + t * NC);
        float4 a0 = p[0], a1 = p[1];   // row t
        float4 b0 = p[2], b1 = p[3];   // row t+1
        float4* w = (float4*)(sinc + t * NC);
        w[0] = make_float4(b0.x - a0.x, b0.y - a0.y, b0.z - a0.z, b0.w - a0.w);
        w[1] = make_float4(b1.x - a1.x, b1.y - a1.y, b1.z - a1.z, b1.w - a1.w);
    }
    __syncthreads();

    const int s0  = g * CHUNK;
    const int len = min(CHUNK, (NL - 1) - s0);

    // Per-step (all RHS uses OLD state):
    //   u    = S1[i]*dx[c] + dx[i]*dx[c]/3
    //   coef = S2[i,c] + u/2
    //   S3[i,c,d] += coef * dx[d]
    //   S2[i,c]   += u + dx[i]*dx[c]/6     (== S1*dxc + dxi*dxc/2)
    //   S1[i]     += dx[i]
    float s1 = 0.f, s2 = 0.f;
    unsigned long long s3[4] = {0ull, 0ull, 0ull, 0ull};

    #pragma unroll 4
    for (int s = 0; s < len; s++) {
        const float* row = sinc + (s0 + s) * NC;
        ulonglong2 dlo = *(const ulonglong2*)(row);       // dx[0..3] packed
        ulonglong2 dhi = *(const ulonglong2*)(row + 4);   // dx[4..7] packed
        float dxi = row[i];   // broadcast LDS
        float dxc = row[c];

        float a    = dxi * dxc;
        float sc   = s1 * dxc;
        float u    = fmaf(a, 1.f / 3.f, sc);
        float coef = fmaf(u, 0.5f, s2);
        unsigned long long coef2;
        asm("mov.b64 %0, {%1, %1};" : "=l"(coef2) : "f"(coef));

        ffma2(s3[0], coef2, dlo.x);
        ffma2(s3[1], coef2, dlo.y);
        ffma2(s3[2], coef2, dhi.x);
        ffma2(s3[3], coef2, dhi.y);

        s2 = fmaf(a, 1.f / 6.f, s2 + u);
        s1 += dxi;
    }

    // Stage this group's segment signature into shared.
    {
        float* S = sseg[g];
        if (lt < 8)   // S1 telescopes to endpoint difference
            S[lt] = prow[(size_t)(s0 + len) * NC + lt] - prow[(size_t)s0 * NC + lt];
        S[S2OFF + lt] = s2;
        ulonglong2* o3 = (ulonglong2*)(sseg[g] + S3OFF + lt * 8);
        ulonglong2 v0; v0.x = s3[0]; v0.y = s3[1];
        ulonglong2 v1; v1.x = s3[2]; v1.y = s3[3];
        o3[0] = v0;
        o3[1] = v1;
    }
    __syncthreads();

    // Tree combine: (0,1)(2,3)(4,5)(6,7) -> (0,2)(4,6) -> (0,4). Chen:
    //   C1 = A1 + B1
    //   C2[i,c]   = A2 + B2 + A1[i]*B1[c]
    //   C3[i,c,d] = A3 + B3 + A1[i]*B2[c,d] + A2[i,c]*B1[d]
    #pragma unroll
    for (int st = 1; st < NG; st <<= 1) {
        const bool active = ((g & (2 * st - 1)) == 0);
        const int  partner = (g + st < NG) ? (g + st) : (NG - 1);
        float na1 = 0.f, na2 = 0.f, na3[8];
        #pragma unroll
        for (int d = 0; d < 8; d++) na3[d] = 0.f;

        float* A = sseg[g];
        const float* B = sseg[partner];

        if (active) {
            float a1i = A[i];
            float a2  = A[S2OFF + lt];
            const float4* a3p = (const float4*)(A + S3OFF + lt * 8);
            float4 av0 = a3p[0], av1 = a3p[1];
            float a3l[8] = {av0.x, av0.y, av0.z, av0.w, av1.x, av1.y, av1.z, av1.w};

            const float4* b1p = (const float4*)(B);
            float4 bv0 = b1p[0], bv1 = b1p[1];
            float b1l[8] = {bv0.x, bv0.y, bv0.z, bv0.w, bv1.x, bv1.y, bv1.z, bv1.w};

            float b2t = B[S2OFF + lt];
            const float4* b2p = (const float4*)(B + S2OFF + c * 8);
            float4 cv0 = b2p[0], cv1 = b2p[1];
            float b2r[8] = {cv0.x, cv0.y, cv0.z, cv0.w, cv1.x, cv1.y, cv1.z, cv1.w};

            const float4* b3p = (const float4*)(B + S3OFF + lt * 8);
            float4 dv0 = b3p[0], dv1 = b3p[1];
            float b3l[8] = {dv0.x, dv0.y, dv0.z, dv0.w, dv1.x, dv1.y, dv1.z, dv1.w};

            #pragma unroll
            for (int d = 0; d < 8; d++)
                na3[d] = fmaf(a2, b1l[d], fmaf(a1i, b2r[d], a3l[d] + b3l[d]));

            na2 = fmaf(a1i, B[c], a2 + b2t);       // B[c] via broadcast LDS
            if (lt < 8) na1 = A[lt] + B[lt];
        }
        __syncthreads();   // all reads done before writes
        if (active) {
            if (lt < 8) A[lt] = na1;
            A[S2OFF + lt] = na2;
            float4* o = (float4*)(A + S3OFF + lt * 8);
            o[0] = make_float4(na3[0], na3[1], na3[2], na3[3]);
            o[1] = make_float4(na3[4], na3[5], na3[6], na3[7]);
        }
        __syncthreads();
    }

    // Final signature sits in sseg[0]; coalesced store.
    float* o = out + (size_t)b * SIGSZ;
    for (int k = t; k < SIGSZ; k += 512)
        o[k] = sseg[0][k];
}

extern "C" void kernel_launch(void* const* d_in, const int* in_sizes, int n_in,
                              void* d_out, int out_size) {
    const float* path = (const float*)d_in[0];
    float* out = (float*)d_out;
    sig_fused_kernel<<<NB, 512>>>(path, out);
}

// round 5
// speedup vs baseline: 1.0960x; 1.0960x over previous
#include <cuda_runtime.h>

#define NB      512
#define NL      512
#define NC      8
#define NCHK    16        // chunks per batch
#define STEPS   32        // increments per chunk (last chunk: 31 real + 1 zero)
#define CSTRIDE 264       // floats per chunk in staging: 32*8 + 8 pad (bank stagger)
#define SIGSZ   584       // 8 + 64 + 512
#define S2OFF   8
#define S3OFF   72

typedef unsigned long long ull;

__device__ __forceinline__ void ffma2(ull& d, ull a, ull b) {
    asm("fma.rn.f32x2 %0, %1, %2, %0;" : "+l"(d) : "l"(a), "l"(b));
}
__device__ __forceinline__ ull fma2n(ull a, ull b, ull c) {
    ull r; asm("fma.rn.f32x2 %0, %1, %2, %3;" : "=l"(r) : "l"(a), "l"(b), "l"(c)); return r;
}
__device__ __forceinline__ ull fmul2(ull a, ull b) {
    ull r; asm("mul.rn.f32x2 %0, %1, %2;" : "=l"(r) : "l"(a), "l"(b)); return r;
}
__device__ __forceinline__ ull fadd2(ull a, ull b) {
    ull r; asm("add.rn.f32x2 %0, %1, %2;" : "=l"(r) : "l"(a), "l"(b)); return r;
}
__device__ __forceinline__ ull dup2(float x) {
    ull r; asm("mov.b64 %0, {%1, %1};" : "=l"(r) : "f"(x)); return r;
}
__device__ __forceinline__ void unpk2(ull v, float& lo, float& hi) {
    asm("mov.b64 {%0, %1}, %2;" : "=f"(lo), "=f"(hi) : "l"(v));
}

// ---------------------------------------------------------------------------
// One block = one batch. 128 threads = 16 chunks x 8 threads.
// Thread (g, i) owns S1[i], S2[i,0..7] (4 x f32x2) and S3[i,c,d] for all
// (c,d): 32 x f32x2 packed over c-pairs: s3[d][cp] = {S3[i][2cp][d], S3[i][2cp+1][d]}.
// Per step (OLD state on RHS), packed over c:
//   a  = dx[i]*dx[c];  sc = S1[i]*dx[c]
//   u  = a/3 + sc;     coef = u/2 + S2[i,c]
//   S3[i,c,d] += coef * dx[d]
//   S2[i,c]   += u + a/6
//   S1[i]     += dx[i]
// Chunk signatures then fold with a 4-level Chen tree in shared memory.
// ---------------------------------------------------------------------------
__global__ __launch_bounds__(128) void sig_fused_kernel(
    const float* __restrict__ path, float* __restrict__ out)
{
    const int b = blockIdx.x;
    const int t = threadIdx.x;     // 0..127
    const int g = t >> 3;          // chunk 0..15
    const int i = t & 7;           // channel row

    // Union: staging (16 chunks * 264 floats = 4224 fl) reused as the segment
    // signature array (16 * 584 = 9344 fl) after the mainloop.
    __shared__ __align__(16) float smem_u[NCHK * SIGSZ];   // 37376 B
    float* sinc = smem_u;
    float* sseg = smem_u;

    const float* prow = path + (size_t)b * NL * NC;

    // ---- Stage increments (chunk-padded layout, zero row for the tail) ----
    for (int r = t; r < NCHK * STEPS; r += 128) {
        float* w = sinc + (r >> 5) * CSTRIDE + (r & 31) * NC;
        if (r < NL - 1) {
            const float4* p = (const float4*)(prow + r * NC);
            float4 a0 = p[0], a1 = p[1], b0 = p[2], b1 = p[3];
            ((float4*)w)[0] = make_float4(b0.x - a0.x, b0.y - a0.y, b0.z - a0.z, b0.w - a0.w);
            ((float4*)w)[1] = make_float4(b1.x - a1.x, b1.y - a1.y, b1.z - a1.z, b1.w - a1.w);
        } else {
            ((float4*)w)[0] = make_float4(0.f, 0.f, 0.f, 0.f);
            ((float4*)w)[1] = make_float4(0.f, 0.f, 0.f, 0.f);
        }
    }
    __syncthreads();

    const ull third2 = dup2(1.f / 3.f);
    const ull half2  = dup2(0.5f);
    const ull sixth2 = dup2(1.f / 6.f);

    float s1 = 0.f;
    ull s2p[4] = {0ull, 0ull, 0ull, 0ull};
    ull s3[8][4];
    #pragma unroll
    for (int d = 0; d < 8; d++)
        #pragma unroll
        for (int cp = 0; cp < 4; cp++) s3[d][cp] = 0ull;

    const float* myc = sinc + g * CSTRIDE;

    #pragma unroll 2
    for (int s = 0; s < STEPS; s++) {
        const float* row = myc + s * NC;
        ulonglong2 lo = *(const ulonglong2*)row;         // {dx0,dx1},{dx2,dx3}
        ulonglong2 hi = *(const ulonglong2*)(row + 4);   // {dx4,dx5},{dx6,dx7}
        ull dx2[4] = {lo.x, lo.y, hi.x, hi.y};
        float dxi = row[i];                               // broadcast LDS
        ull dxi2 = dup2(dxi);
        ull s12  = dup2(s1);

        ull coef[4];
        #pragma unroll
        for (int cp = 0; cp < 4; cp++) {
            ull a2  = fmul2(dxi2, dx2[cp]);
            ull sc2 = fmul2(s12, dx2[cp]);
            ull u2  = fma2n(a2, third2, sc2);
            coef[cp] = fma2n(u2, half2, s2p[cp]);
            s2p[cp]  = fma2n(a2, sixth2, fadd2(s2p[cp], u2));
        }

        #pragma unroll
        for (int dp = 0; dp < 4; dp++) {
            float dl, dh; unpk2(dx2[dp], dl, dh);
            ull dl2 = dup2(dl), dh2 = dup2(dh);
            #pragma unroll
            for (int cp = 0; cp < 4; cp++) {
                ffma2(s3[2 * dp][cp],     coef[cp], dl2);
                ffma2(s3[2 * dp + 1][cp], coef[cp], dh2);
            }
        }
        s1 += dxi;
    }

    __syncthreads();   // all reads of sinc done before sseg overwrites it

    // ---- Write segment signature ----
    {
        float* S = sseg + g * SIGSZ;
        S[i] = s1;                                // S1 (accumulated == telescoped)
        #pragma unroll
        for (int cp = 0; cp < 4; cp++)
            *(ull*)(S + S2OFF + i * 8 + 2 * cp) = s2p[cp];
        #pragma unroll
        for (int d = 0; d < 8; d++)
            #pragma unroll
            for (int cp = 0; cp < 4; cp++) {
                float v0, v1; unpk2(s3[d][cp], v0, v1);
                S[S3OFF + i * 64 + (2 * cp) * 8 + d]     = v0;
                S[S3OFF + i * 64 + (2 * cp + 1) * 8 + d] = v1;
            }
    }
    __syncthreads();

    // ---- Chen tree combine: 16 -> 8 -> 4 -> 2 -> 1 (result in sseg[0]) ----
    //   C1 = A1 + B1
    //   C2[i,c]   = A2 + B2 + A1[i]*B1[c]
    //   C3[i,c,d] = A3 + B3 + A1[i]*B2[c,d] + A2[i,c]*B1[d]
    #pragma unroll
    for (int st = 1; st < NCHK; st <<= 1) {
        const int nm = NCHK / (2 * st);       // merges this level
        const int work = nm * 64;
        for (int base = 0; base < work; base += 128) {
            const int w = base + t;
            const bool act = w < work;
            const int m  = w >> 6;
            const int lt = w & 63;
            const int i2 = lt >> 3;
            const int c2 = lt & 7;
            float* A = sseg + (size_t)(2 * st * m) * SIGSZ;
            const float* B = sseg + (size_t)(2 * st * m + st) * SIGSZ;

            float na1 = 0.f, na2 = 0.f, na3[8];
            #pragma unroll
            for (int d = 0; d < 8; d++) na3[d] = 0.f;

            if (act) {
                float a1i = A[i2];
                float a2  = A[S2OFF + lt];
                const float4* a3p = (const float4*)(A + S3OFF + lt * 8);
                float4 av0 = a3p[0], av1 = a3p[1];
                float a3l[8] = {av0.x, av0.y, av0.z, av0.w, av1.x, av1.y, av1.z, av1.w};

                const float4* b1p = (const float4*)B;
                float4 bv0 = b1p[0], bv1 = b1p[1];
                float b1l[8] = {bv0.x, bv0.y, bv0.z, bv0.w, bv1.x, bv1.y, bv1.z, bv1.w};

                float b2t = B[S2OFF + lt];
                const float4* b2p = (const float4*)(B + S2OFF + c2 * 8);
                float4 cv0 = b2p[0], cv1 = b2p[1];
                float b2r[8] = {cv0.x, cv0.y, cv0.z, cv0.w, cv1.x, cv1.y, cv1.z, cv1.w};

                const float4* b3p = (const float4*)(B + S3OFF + lt * 8);
                float4 dv0 = b3p[0], dv1 = b3p[1];
                float b3l[8] = {dv0.x, dv0.y, dv0.z, dv0.w, dv1.x, dv1.y, dv1.z, dv1.w};

                #pragma unroll
                for (int d = 0; d < 8; d++)
                    na3[d] = fmaf(a2, b1l[d], fmaf(a1i, b2r[d], a3l[d] + b3l[d]));

                na2 = fmaf(a1i, b1l[c2], a2 + b2t);
                if (lt < 8) na1 = A[lt] + B[lt];
            }
            __syncthreads();   // reads complete before writes
            if (act) {
                if (lt < 8) A[lt] = na1;
                A[S2OFF + lt] = na2;
                float4* o = (float4*)(A + S3OFF + lt * 8);
                o[0] = make_float4(na3[0], na3[1], na3[2], na3[3]);
                o[1] = make_float4(na3[4], na3[5], na3[6], na3[7]);
            }
            __syncthreads();
        }
    }

    // ---- Store final signature (coalesced) ----
    float* o = out + (size_t)b * SIGSZ;
    for (int k = t; k < SIGSZ; k += 128)
        o[k] = sseg[k];
}

extern "C" void kernel_launch(void* const* d_in, const int* in_sizes, int n_in,
                              void* d_out, int out_size) {
    const float* path = (const float*)d_in[0];
    float* out = (float*)d_out;
    sig_fused_kernel<<<NB, 128>>>(path, out);
}